// round 12
// baseline (speedup 1.0000x reference)
#include <cuda_runtime.h>
#include <cuda_fp16.h>
#include <cstdint>

#define B_    32
#define SQ_   2048
#define SKV_  2048
#define D_    128
#define MT    128
#define NT    64
#define NTILES (SKV_/NT)
#define NTHREADS 256

#define INV_KEEP  (1.0f/0.7f)
#define LOG2E_F   1.4426950408889634f
// keep <=> tf_bits < KEEP_THRESH (exact integer form of u < 0.7f, validated R9)
#define KEEP_THRESH 0xB3333400u

#define ROWB 272          // row stride bytes (136 fp16) -> LDSM conflict-free

enum {
  OFF_QH = 0, OFF_QL = 34816,                    // Q planes: 128*272
  OFF_BUF0 = 69632, OFF_BUF1 = 139264,           // K/V double buffer
  BUF_KH = 0, BUF_KL = 17408, BUF_VH = 34816, BUF_VL = 52224,
  SMEM_TOTAL = 208896
};

// global scratch: fp16 2-way split planes (prep kernel fills once per launch)
#define NV4 1048576
__device__ uint4 g_QH[NV4], g_QL[NV4];
__device__ uint4 g_KH[NV4], g_KL[NV4];
__device__ uint4 g_VH[NV4], g_VL[NV4];

// ---------------------------------------------------------------------------
// JAX threefry2x32, key=(0,42); bits = x0 ^ x1 (validated R2)
// ---------------------------------------------------------------------------
__device__ __forceinline__ uint32_t rotl32(uint32_t x, int d) { return __funnelshift_l(x, x, d); }
__device__ __forceinline__ void tf_round(uint32_t& x0, uint32_t& x1, int r) {
    x0 += x1; x1 = rotl32(x1, r) ^ x0;
}
__device__ __forceinline__ uint32_t tf_bits(uint32_t idx) {
    const uint32_t ks0 = 0u, ks1 = 42u, ks2 = 0x1BD11BDAu ^ 42u;
    uint32_t x0 = 0u, x1 = idx;
    x0 += ks0; x1 += ks1;
    tf_round(x0, x1, 13); tf_round(x0, x1, 15); tf_round(x0, x1, 26); tf_round(x0, x1, 6);
    x0 += ks1; x1 += ks2 + 1u;
    tf_round(x0, x1, 17); tf_round(x0, x1, 29); tf_round(x0, x1, 16); tf_round(x0, x1, 24);
    x0 += ks2; x1 += ks0 + 2u;
    tf_round(x0, x1, 13); tf_round(x0, x1, 15); tf_round(x0, x1, 26); tf_round(x0, x1, 6);
    x0 += ks0; x1 += ks1 + 3u;
    tf_round(x0, x1, 17); tf_round(x0, x1, 29); tf_round(x0, x1, 16); tf_round(x0, x1, 24);
    x0 += ks1; x1 += ks2 + 4u;
    tf_round(x0, x1, 13); tf_round(x0, x1, 15); tf_round(x0, x1, 26); tf_round(x0, x1, 6);
    x0 += ks2; x1 += ks0 + 5u;
    return x0 ^ x1;
}

__device__ __forceinline__ uint32_t pack2h(__half a, __half b) {
    return (uint32_t)__half_as_ushort(a) | ((uint32_t)__half_as_ushort(b) << 16);
}
__device__ __forceinline__ uint32_t packh2(float lo, float hi) {
    uint32_t d;
    asm("cvt.rn.f16x2.f32 %0, %1, %2;" : "=r"(d) : "f"(hi), "f"(lo));
    return d;
}
__device__ __forceinline__ void split2h(float x, __half& h, __half& l) {
    h = __float2half_rn(x);
    l = __float2half_rn(x - __half2float(h));
}

__device__ __forceinline__ uint32_t smem_u32(const void* p) {
    uint32_t a;
    asm("{ .reg .u64 t; cvta.to.shared.u64 t, %1; cvt.u32.u64 %0, t; }" : "=r"(a) : "l"(p));
    return a;
}
__device__ __forceinline__ void mma_h(float c[4], const uint32_t a[4], const uint32_t b[2]) {
    asm volatile("mma.sync.aligned.m16n8k16.row.col.f32.f16.f16.f32 "
        "{%0,%1,%2,%3}, {%4,%5,%6,%7}, {%8,%9}, {%0,%1,%2,%3};"
        : "+f"(c[0]), "+f"(c[1]), "+f"(c[2]), "+f"(c[3])
        : "r"(a[0]), "r"(a[1]), "r"(a[2]), "r"(a[3]), "r"(b[0]), "r"(b[1]));
}
__device__ __forceinline__ void ldsm4(uint32_t r[4], uint32_t addr) {
    asm volatile("ldmatrix.sync.aligned.m8n8.x4.shared.b16 {%0,%1,%2,%3}, [%4];"
        : "=r"(r[0]), "=r"(r[1]), "=r"(r[2]), "=r"(r[3]) : "r"(addr));
}
__device__ __forceinline__ void ldsm4t(uint32_t r[4], uint32_t addr) {
    asm volatile("ldmatrix.sync.aligned.m8n8.x4.trans.shared.b16 {%0,%1,%2,%3}, [%4];"
        : "=r"(r[0]), "=r"(r[1]), "=r"(r[2]), "=r"(r[3]) : "r"(addr));
}
__device__ __forceinline__ void cpasync16(uint32_t dst, const void* src) {
    asm volatile("cp.async.cg.shared.global [%0], [%1], 16;" :: "r"(dst), "l"(src));
}
#define CP_COMMIT() asm volatile("cp.async.commit_group;" ::: "memory")
#define CP_WAIT1()  asm volatile("cp.async.wait_group 1;" ::: "memory")
#define CP_WAIT0()  asm volatile("cp.async.wait_group 0;" ::: "memory")

// ---------------------------------------------------------------------------
// Prep: fp16 2-way split of Q (scale folded), K, V into global planes
// ---------------------------------------------------------------------------
#define NQ4 2097152
__global__ void __launch_bounds__(256) prep_kernel(const float* __restrict__ q,
                                                   const float* __restrict__ k,
                                                   const float* __restrict__ v,
                                                   const float* __restrict__ sf) {
    int i = blockIdx.x * 256 + threadIdx.x;
    float4 x;
    uint2 *dh, *dl;
    int j;
    if (i < NQ4) {
        x = ((const float4*)q)[i];
        float s = sf[i >> 16];
        x.x *= s; x.y *= s; x.z *= s; x.w *= s;
        dh = (uint2*)g_QH; dl = (uint2*)g_QL; j = i;
    } else if (i < 2 * NQ4) {
        j = i - NQ4;
        x = ((const float4*)k)[j];
        dh = (uint2*)g_KH; dl = (uint2*)g_KL;
    } else {
        j = i - 2 * NQ4;
        x = ((const float4*)v)[j];
        dh = (uint2*)g_VH; dl = (uint2*)g_VL;
    }
    __half h[4], l[4];
    split2h(x.x, h[0], l[0]); split2h(x.y, h[1], l[1]);
    split2h(x.z, h[2], l[2]); split2h(x.w, h[3], l[3]);
    dh[j] = make_uint2(pack2h(h[0], h[1]), pack2h(h[2], h[3]));
    dl[j] = make_uint2(pack2h(l[0], l[1]), pack2h(l[2], l[3]));
}

// ---------------------------------------------------------------------------
// Main attention kernel
// ---------------------------------------------------------------------------
__global__ void __launch_bounds__(NTHREADS, 1)
attn_fa5_kernel(float* __restrict__ out) {
    extern __shared__ char smem[];
    const uint32_t sb = smem_u32(smem);

    const int b    = blockIdx.y;
    const int q0   = blockIdx.x * MT;
    const int tid  = threadIdx.x;
    const int w    = tid >> 5;
    const int lane = tid & 31;
    const int g    = lane >> 2;
    const int tig  = lane & 3;
    const int m0   = w * 16;
    const int l7   = lane & 7;
    const int b3   = (lane >> 3) & 1;
    const int b4   = lane >> 4;

    const uint32_t aBase   = sb + OFF_QH + (uint32_t)((m0 + l7 + 8 * b3) * ROWB + 16 * b4);
    const uint32_t kLaneOf = (uint32_t)((l7 + 8 * b4) * ROWB + 16 * b3);
    const uint32_t vLaneOf = (uint32_t)((l7 + 8 * b3) * ROWB + 16 * b4);

    // ---- stage Q planes (pure LDG.128 -> STS.128) ----
    {
        const int qrow0 = (b * SQ_ + q0) * 16;
#pragma unroll
        for (int c = 0; c < 8; c++) {
            int f = tid + 256 * c;
            int rr = f >> 4, c4 = f & 15;
            *(uint4*)(smem + OFF_QH + rr * ROWB + c4 * 16) = g_QH[qrow0 + rr * 16 + c4];
            *(uint4*)(smem + OFF_QL + rr * ROWB + c4 * 16) = g_QL[qrow0 + rr * 16 + c4];
        }
    }

    float O[16][4];
#pragma unroll
    for (int nt = 0; nt < 16; nt++) { O[nt][0] = O[nt][1] = O[nt][2] = O[nt][3] = 0.0f; }
    float mr0 = -3.402823466e38f, mr1 = -3.402823466e38f, lr0 = 0.0f, lr1 = 0.0f;

    // per-thread threefry base index: row (rowbase+g), col kv0 + 2*tig
    const uint32_t rowbase = (uint32_t)(b * SQ_ + q0 + m0);
    const uint32_t idxTile0 = (rowbase + (uint32_t)g) * (uint32_t)SKV_ + (uint32_t)(2 * tig);
    const int bkb = b * SKV_;

    // prologue: stage tile 0 into buf0; compute mask(0) rows g+8 (sub 2,3)
    {
        const uint4* gp[4] = {g_KH, g_KL, g_VH, g_VL};
#pragma unroll
        for (int s = 0; s < 4; s++)
#pragma unroll
            for (int c = 0; c < 4; c++) {
                int f = tid + 256 * c;
                int rr = f >> 4, c4 = f & 15;
                cpasync16(sb + OFF_BUF0 + (uint32_t)(s * 17408 + rr * ROWB + c4 * 16),
                          &gp[s][(bkb + rr) * 16 + c4]);
            }
        CP_COMMIT();
    }
    uint32_t kmB = 0;   // mask bits for rows g+8 of the UPCOMING tile
    {
        const uint32_t base = idxTile0 + 8u * (uint32_t)SKV_;
#pragma unroll
        for (int vv = 0; vv < 16; vv++) {
            uint32_t idx = base + (uint32_t)(8 * (vv >> 1) + (vv & 1));
            kmB |= (tf_bits(idx) < KEEP_THRESH) ? (1u << vv) : 0u;
        }
    }

    for (int t = 0; t < NTILES; t++) {
        __syncthreads();

        if (t + 1 < NTILES) {
            const uint32_t nbuf = sb + (((t + 1) & 1) ? OFF_BUF1 : OFF_BUF0);
            const int bk = bkb + (t + 1) * NT;
            const uint4* gp[4] = {g_KH, g_KL, g_VH, g_VL};
#pragma unroll
            for (int s = 0; s < 4; s++)
#pragma unroll
                for (int c = 0; c < 4; c++) {
                    int f = tid + 256 * c;
                    int rr = f >> 4, c4 = f & 15;
                    cpasync16(nbuf + (uint32_t)(s * 17408 + rr * ROWB + c4 * 16),
                              &gp[s][(bk + rr) * 16 + c4]);
                }
            CP_COMMIT();
            CP_WAIT1();
        } else {
            CP_WAIT0();
        }
        __syncthreads();

        const uint32_t bufb  = sb + ((t & 1) ? OFF_BUF1 : OFF_BUF0);
        const uint32_t kBase = bufb + BUF_KH + kLaneOf;
        const uint32_t vBase = bufb + BUF_VH + vLaneOf;
        const uint32_t idxT  = idxTile0 + (uint32_t)(t * NT);

        // ---- QK MMAs (3 fp16 passes) + mask(t) rows g (sub 0,1) interleaved ----
        float sacc[8][4];
#pragma unroll
        for (int nt = 0; nt < 8; nt++) { sacc[nt][0] = sacc[nt][1] = sacc[nt][2] = sacc[nt][3] = 0.0f; }

        uint32_t kmA = 0;
#pragma unroll
        for (int k8 = 0; k8 < 8; k8++) {
            {   // 2 threefry evals (row g, cols 8*k8 + {0,1}) — overlaps HMMA
                uint32_t ia = idxT + (uint32_t)(8 * k8);
                kmA |= (tf_bits(ia)      < KEEP_THRESH) ? (1u << (2 * k8)) : 0u;
                kmA |= (tf_bits(ia + 1u) < KEEP_THRESH) ? (2u << (2 * k8)) : 0u;
            }
            uint32_t aH[4], aL[4];
            const uint32_t aAddr = aBase + (uint32_t)(k8 * 32);
            ldsm4(aH, aAddr);
            ldsm4(aL, aAddr + 34816u);
#pragma unroll
            for (int ntp = 0; ntp < 4; ntp++) {
                const uint32_t kAddr = kBase + (uint32_t)(ntp * 16 * ROWB + k8 * 32);
                uint32_t kH[4], kL[4];
                ldsm4(kH, kAddr);
                ldsm4(kL, kAddr + 17408u);
                mma_h(sacc[2 * ntp], aH, kH);
                mma_h(sacc[2 * ntp], aH, kL);
                mma_h(sacc[2 * ntp], aL, kH);
                mma_h(sacc[2 * ntp + 1], aH, kH + 2);
                mma_h(sacc[2 * ntp + 1], aH, kL + 2);
                mma_h(sacc[2 * ntp + 1], aL, kH + 2);
            }
        }

        // ---- softmax + dropout (kmA = rows g now, kmB = rows g+8 from last PV) ----
        float mx0 = sacc[0][0], mx1 = sacc[0][2];
#pragma unroll
        for (int nt = 0; nt < 8; nt++) {
            mx0 = fmaxf(mx0, fmaxf(sacc[nt][0], sacc[nt][1]));
            mx1 = fmaxf(mx1, fmaxf(sacc[nt][2], sacc[nt][3]));
        }
        mx0 = fmaxf(mx0, __shfl_xor_sync(0xffffffffu, mx0, 1));
        mx0 = fmaxf(mx0, __shfl_xor_sync(0xffffffffu, mx0, 2));
        mx1 = fmaxf(mx1, __shfl_xor_sync(0xffffffffu, mx1, 1));
        mx1 = fmaxf(mx1, __shfl_xor_sync(0xffffffffu, mx1, 2));
        float mn0 = fmaxf(mr0, mx0), mn1 = fmaxf(mr1, mx1);
        float al0 = exp2f((mr0 - mn0) * LOG2E_F);
        float al1 = exp2f((mr1 - mn1) * LOG2E_F);

        uint32_t pHa[8], pHb[8];
        float ls0 = 0.0f, ls1 = 0.0f;
#pragma unroll
        for (int nt = 0; nt < 8; nt++) {
            float p0 = exp2f((sacc[nt][0] - mn0) * LOG2E_F);
            float p1 = exp2f((sacc[nt][1] - mn0) * LOG2E_F);
            float p2 = exp2f((sacc[nt][2] - mn1) * LOG2E_F);
            float p3 = exp2f((sacc[nt][3] - mn1) * LOG2E_F);
            ls0 += p0 + p1; ls1 += p2 + p3;
            uint32_t ma = kmA >> (2 * nt), mb = kmB >> (2 * nt);
            float d0 = (ma & 1u) ? p0 * INV_KEEP : 0.0f;
            float d1 = (ma & 2u) ? p1 * INV_KEEP : 0.0f;
            float d2 = (mb & 1u) ? p2 * INV_KEEP : 0.0f;
            float d3 = (mb & 2u) ? p3 * INV_KEEP : 0.0f;
            pHa[nt] = packh2(d0, d1);
            pHb[nt] = packh2(d2, d3);
        }
        ls0 += __shfl_xor_sync(0xffffffffu, ls0, 1);
        ls0 += __shfl_xor_sync(0xffffffffu, ls0, 2);
        ls1 += __shfl_xor_sync(0xffffffffu, ls1, 1);
        ls1 += __shfl_xor_sync(0xffffffffu, ls1, 2);
        lr0 = lr0 * al0 + ls0;
        lr1 = lr1 * al1 + ls1;
        mr0 = mn0; mr1 = mn1;

#pragma unroll
        for (int nt = 0; nt < 16; nt++) {
            O[nt][0] *= al0; O[nt][1] *= al0;
            O[nt][2] *= al1; O[nt][3] *= al1;
        }

        // ---- PV: O += P * V (vH only) + mask(t+1) rows g+8 interleaved ----
        kmB = 0;
        const uint32_t idxN = idxT + (uint32_t)NT + 8u * (uint32_t)SKV_;
#pragma unroll
        for (int kkp = 0; kkp < 4; kkp++) {
            uint32_t aH[4] = { pHa[2 * kkp], pHb[2 * kkp], pHa[2 * kkp + 1], pHb[2 * kkp + 1] };
#pragma unroll
            for (int ntp = 0; ntp < 8; ntp++) {
                const int p = kkp * 8 + ntp;
                if (p < 16) {   // 1 threefry eval for next tile's rows g+8
                    uint32_t idx = idxN + (uint32_t)(8 * (p >> 1) + (p & 1));
                    kmB |= (tf_bits(idx) < KEEP_THRESH) ? (1u << p) : 0u;
                }
                const uint32_t vAddr = vBase + (uint32_t)(kkp * 16 * ROWB + ntp * 32);
                uint32_t vH[4];
                ldsm4t(vH, vAddr);
                mma_h(O[2 * ntp], aH, vH);
                mma_h(O[2 * ntp + 1], aH, vH + 2);
            }
        }
    }

    // ---- final: O / l -> gmem ----
    {
        float inv0 = 1.0f / lr0, inv1 = 1.0f / lr1;
        long row0 = (long)(b * SQ_ + q0 + m0 + g);
        float* o0 = out + row0 * D_ + 2 * tig;
        float* o1 = out + (row0 + 8) * D_ + 2 * tig;
#pragma unroll
        for (int nt = 0; nt < 16; nt++) {
            *(float2*)(o0 + 8 * nt) = make_float2(O[nt][0] * inv0, O[nt][1] * inv0);
            *(float2*)(o1 + 8 * nt) = make_float2(O[nt][2] * inv1, O[nt][3] * inv1);
        }
    }
}

// ---------------------------------------------------------------------------
extern "C" void kernel_launch(void* const* d_in, const int* in_sizes, int n_in,
                              void* d_out, int out_size) {
    const float* q  = (const float*)d_in[0];
    const float* k  = (const float*)d_in[1];
    const float* v  = (const float*)d_in[2];
    const float* sf = (const float*)d_in[3];
    float* out = (float*)d_out;

    prep_kernel<<<3 * NQ4 / 256, 256>>>(q, k, v, sf);

    cudaFuncSetAttribute(attn_fa5_kernel,
                         cudaFuncAttributeMaxDynamicSharedMemorySize, SMEM_TOTAL);
    dim3 grid(SQ_ / MT, B_);
    attn_fa5_kernel<<<grid, NTHREADS, SMEM_TOTAL>>>(out);
}

// round 14
// speedup vs baseline: 1.5617x; 1.5617x over previous
#include <cuda_runtime.h>
#include <cuda_fp16.h>
#include <cstdint>

#define B_    32
#define SQ_   2048
#define SKV_  2048
#define D_    128
#define MT    128
#define NT    64
#define NTILES (SKV_/NT)
#define NTHREADS 256

#define INV_KEEP  (1.0f/0.7f)
#define LOG2E_F   1.4426950408889634f
// keep <=> tf_bits < KEEP_THRESH (exact integer form of u < 0.7f, validated R9)
#define KEEP_THRESH 0xB3333400u

#define ROWB 272          // row stride bytes (136 fp16) -> LDSM conflict-free

enum {
  OFF_QH = 0, OFF_QL = 34816,                    // Q planes: 128*272
  OFF_BUF0 = 69632, OFF_BUF1 = 121856,           // K/V double buffer (3 planes each)
  BUF_KH = 0, BUF_KL = 17408, BUF_VH = 34816,
  SMEM_TOTAL = 174080
};

// global scratch: fp16 split planes (prep kernel fills once per launch)
#define NV4 1048576
__device__ uint4 g_QH[NV4], g_QL[NV4];
__device__ uint4 g_KH[NV4], g_KL[NV4];
__device__ uint4 g_VH[NV4];

// ---------------------------------------------------------------------------
// JAX threefry2x32, key=(0,42); bits = x0 ^ x1 (validated R2)
// ---------------------------------------------------------------------------
__device__ __forceinline__ uint32_t rotl32(uint32_t x, int d) { return __funnelshift_l(x, x, d); }
__device__ __forceinline__ void tf_round(uint32_t& x0, uint32_t& x1, int r) {
    x0 += x1; x1 = rotl32(x1, r) ^ x0;
}
__device__ __forceinline__ uint32_t tf_bits(uint32_t idx) {
    const uint32_t ks0 = 0u, ks1 = 42u, ks2 = 0x1BD11BDAu ^ 42u;
    uint32_t x0 = 0u, x1 = idx;
    x0 += ks0; x1 += ks1;
    tf_round(x0, x1, 13); tf_round(x0, x1, 15); tf_round(x0, x1, 26); tf_round(x0, x1, 6);
    x0 += ks1; x1 += ks2 + 1u;
    tf_round(x0, x1, 17); tf_round(x0, x1, 29); tf_round(x0, x1, 16); tf_round(x0, x1, 24);
    x0 += ks2; x1 += ks0 + 2u;
    tf_round(x0, x1, 13); tf_round(x0, x1, 15); tf_round(x0, x1, 26); tf_round(x0, x1, 6);
    x0 += ks0; x1 += ks1 + 3u;
    tf_round(x0, x1, 17); tf_round(x0, x1, 29); tf_round(x0, x1, 16); tf_round(x0, x1, 24);
    x0 += ks1; x1 += ks2 + 4u;
    tf_round(x0, x1, 13); tf_round(x0, x1, 15); tf_round(x0, x1, 26); tf_round(x0, x1, 6);
    x0 += ks2; x1 += ks0 + 5u;
    return x0 ^ x1;
}

__device__ __forceinline__ uint32_t pack2h(__half a, __half b) {
    return (uint32_t)__half_as_ushort(a) | ((uint32_t)__half_as_ushort(b) << 16);
}
__device__ __forceinline__ uint32_t packh2(float lo, float hi) {
    uint32_t d;
    asm("cvt.rn.f16x2.f32 %0, %1, %2;" : "=r"(d) : "f"(hi), "f"(lo));
    return d;
}
__device__ __forceinline__ void split2h(float x, __half& h, __half& l) {
    h = __float2half_rn(x);
    l = __float2half_rn(x - __half2float(h));
}

__device__ __forceinline__ uint32_t smem_u32(const void* p) {
    uint32_t a;
    asm("{ .reg .u64 t; cvta.to.shared.u64 t, %1; cvt.u32.u64 %0, t; }" : "=r"(a) : "l"(p));
    return a;
}
__device__ __forceinline__ void mma_h(float c[4], const uint32_t a[4], const uint32_t b[2]) {
    asm volatile("mma.sync.aligned.m16n8k16.row.col.f32.f16.f16.f32 "
        "{%0,%1,%2,%3}, {%4,%5,%6,%7}, {%8,%9}, {%0,%1,%2,%3};"
        : "+f"(c[0]), "+f"(c[1]), "+f"(c[2]), "+f"(c[3])
        : "r"(a[0]), "r"(a[1]), "r"(a[2]), "r"(a[3]), "r"(b[0]), "r"(b[1]));
}
__device__ __forceinline__ void ldsm4(uint32_t r[4], uint32_t addr) {
    asm volatile("ldmatrix.sync.aligned.m8n8.x4.shared.b16 {%0,%1,%2,%3}, [%4];"
        : "=r"(r[0]), "=r"(r[1]), "=r"(r[2]), "=r"(r[3]) : "r"(addr));
}
__device__ __forceinline__ void ldsm4t(uint32_t r[4], uint32_t addr) {
    asm volatile("ldmatrix.sync.aligned.m8n8.x4.trans.shared.b16 {%0,%1,%2,%3}, [%4];"
        : "=r"(r[0]), "=r"(r[1]), "=r"(r[2]), "=r"(r[3]) : "r"(addr));
}
__device__ __forceinline__ void cpasync16(uint32_t dst, const void* src) {
    asm volatile("cp.async.cg.shared.global [%0], [%1], 16;" :: "r"(dst), "l"(src));
}
#define CP_COMMIT() asm volatile("cp.async.commit_group;" ::: "memory")
#define CP_WAIT1()  asm volatile("cp.async.wait_group 1;" ::: "memory")
#define CP_WAIT0()  asm volatile("cp.async.wait_group 0;" ::: "memory")

// ---------------------------------------------------------------------------
// Prep: fp16 2-way split of Q (scale folded), K; fp16 high plane of V
// ---------------------------------------------------------------------------
#define NQ4 2097152
__global__ void __launch_bounds__(256) prep_kernel(const float* __restrict__ q,
                                                   const float* __restrict__ k,
                                                   const float* __restrict__ v,
                                                   const float* __restrict__ sf) {
    int i = blockIdx.x * 256 + threadIdx.x;
    if (i < NQ4) {
        float4 x = ((const float4*)q)[i];
        float s = sf[i >> 16];
        x.x *= s; x.y *= s; x.z *= s; x.w *= s;
        __half h[4], l[4];
        split2h(x.x, h[0], l[0]); split2h(x.y, h[1], l[1]);
        split2h(x.z, h[2], l[2]); split2h(x.w, h[3], l[3]);
        ((uint2*)g_QH)[i] = make_uint2(pack2h(h[0], h[1]), pack2h(h[2], h[3]));
        ((uint2*)g_QL)[i] = make_uint2(pack2h(l[0], l[1]), pack2h(l[2], l[3]));
    } else if (i < 2 * NQ4) {
        int j = i - NQ4;
        float4 x = ((const float4*)k)[j];
        __half h[4], l[4];
        split2h(x.x, h[0], l[0]); split2h(x.y, h[1], l[1]);
        split2h(x.z, h[2], l[2]); split2h(x.w, h[3], l[3]);
        ((uint2*)g_KH)[j] = make_uint2(pack2h(h[0], h[1]), pack2h(h[2], h[3]));
        ((uint2*)g_KL)[j] = make_uint2(pack2h(l[0], l[1]), pack2h(l[2], l[3]));
    } else {
        int j = i - 2 * NQ4;
        float4 x = ((const float4*)v)[j];
        ((uint2*)g_VH)[j] = make_uint2(packh2(x.x, x.y), packh2(x.z, x.w));
    }
}

// ---------------------------------------------------------------------------
// Main attention kernel (structure == R11; PV uses vH only)
// ---------------------------------------------------------------------------
__global__ void __launch_bounds__(NTHREADS, 1)
attn_fa6_kernel(float* __restrict__ out) {
    extern __shared__ char smem[];
    const uint32_t sb = smem_u32(smem);

    const int b    = blockIdx.y;
    const int q0   = blockIdx.x * MT;
    const int tid  = threadIdx.x;
    const int lane = tid & 31;
    const int w    = tid >> 5;
    const int g    = lane >> 2;
    const int tig  = lane & 3;
    const int m0   = w * 16;
    const int l7   = lane & 7;
    const int b3   = (lane >> 3) & 1;
    const int b4   = lane >> 4;

    const uint32_t aBase   = sb + OFF_QH + (uint32_t)((m0 + l7 + 8 * b3) * ROWB + 16 * b4);
    const uint32_t kLaneOf = (uint32_t)((l7 + 8 * b4) * ROWB + 16 * b3);
    const uint32_t vLaneOf = (uint32_t)((l7 + 8 * b3) * ROWB + 16 * b4);

    // ---- stage Q planes (pure LDG.128 -> STS.128) ----
    {
        const int qrow0 = (b * SQ_ + q0) * 16;
#pragma unroll
        for (int c = 0; c < 8; c++) {
            int f = tid + 256 * c;
            int rr = f >> 4, c4 = f & 15;
            *(uint4*)(smem + OFF_QH + rr * ROWB + c4 * 16) = g_QH[qrow0 + rr * 16 + c4];
            *(uint4*)(smem + OFF_QL + rr * ROWB + c4 * 16) = g_QL[qrow0 + rr * 16 + c4];
        }
    }

    float O[16][4];
#pragma unroll
    for (int nt = 0; nt < 16; nt++) { O[nt][0] = O[nt][1] = O[nt][2] = O[nt][3] = 0.0f; }
    float mr0 = -3.402823466e38f, mr1 = -3.402823466e38f, lr0 = 0.0f, lr1 = 0.0f;

    const uint32_t rowbase = (uint32_t)(b * SQ_ + q0 + m0);
    const int bkb = b * SKV_;

    // prologue: stage tile 0 into buf0
    {
        const uint4* gp[3] = {g_KH, g_KL, g_VH};
#pragma unroll
        for (int s = 0; s < 3; s++)
#pragma unroll
            for (int c = 0; c < 4; c++) {
                int f = tid + 256 * c;
                int rr = f >> 4, c4 = f & 15;
                cpasync16(sb + OFF_BUF0 + (uint32_t)(s * 17408 + rr * ROWB + c4 * 16),
                          &gp[s][(bkb + rr) * 16 + c4]);
            }
        CP_COMMIT();
    }

    for (int t = 0; t < NTILES; t++) {
        const int kv0 = t * NT;
        __syncthreads();

        if (t + 1 < NTILES) {
            const uint32_t nbuf = sb + (((t + 1) & 1) ? OFF_BUF1 : OFF_BUF0);
            const int bk = bkb + (t + 1) * NT;
            const uint4* gp[3] = {g_KH, g_KL, g_VH};
#pragma unroll
            for (int s = 0; s < 3; s++)
#pragma unroll
                for (int c = 0; c < 4; c++) {
                    int f = tid + 256 * c;
                    int rr = f >> 4, c4 = f & 15;
                    cpasync16(nbuf + (uint32_t)(s * 17408 + rr * ROWB + c4 * 16),
                              &gp[s][(bk + rr) * 16 + c4]);
                }
            CP_COMMIT();
            CP_WAIT1();
        } else {
            CP_WAIT0();
        }
        __syncthreads();

        const uint32_t bufb  = sb + ((t & 1) ? OFF_BUF1 : OFF_BUF0);
        const uint32_t kBase = bufb + BUF_KH + kLaneOf;
        const uint32_t vBase = bufb + BUF_VH + vLaneOf;

        // ---- QK MMAs (3 fp16 passes: HH, HL, LH) + threefry interleaved ----
        float sacc[8][4];
#pragma unroll
        for (int nt = 0; nt < 8; nt++) { sacc[nt][0] = sacc[nt][1] = sacc[nt][2] = sacc[nt][3] = 0.0f; }

        uint32_t kmask = 0;
        const uint32_t idx00 = (rowbase + (uint32_t)g) * (uint32_t)SKV_
                             + (uint32_t)(kv0 + 2 * tig);

#pragma unroll
        for (int k8 = 0; k8 < 8; k8++) {
            {   // dropout mask for n-tile k8 (ALU, overlaps HMMA) — R11 shape
                uint32_t ia = idx00 + (uint32_t)(8 * k8);
                uint32_t ib = ia + 8u * (uint32_t)SKV_;
                uint32_t q0b = (tf_bits(ia)      < KEEP_THRESH) ? 1u : 0u;
                uint32_t q1b = (tf_bits(ia + 1u) < KEEP_THRESH) ? 2u : 0u;
                uint32_t q2b = (tf_bits(ib)      < KEEP_THRESH) ? 4u : 0u;
                uint32_t q3b = (tf_bits(ib + 1u) < KEEP_THRESH) ? 8u : 0u;
                kmask |= (q0b | q1b | q2b | q3b) << (4 * k8);
            }
            uint32_t aH[4], aL[4];
            const uint32_t aAddr = aBase + (uint32_t)(k8 * 32);
            ldsm4(aH, aAddr);
            ldsm4(aL, aAddr + 34816u);
#pragma unroll
            for (int ntp = 0; ntp < 4; ntp++) {
                const uint32_t kAddr = kBase + (uint32_t)(ntp * 16 * ROWB + k8 * 32);
                uint32_t kH[4], kL[4];
                ldsm4(kH, kAddr);
                ldsm4(kL, kAddr + 17408u);
                mma_h(sacc[2 * ntp], aH, kH);
                mma_h(sacc[2 * ntp], aH, kL);
                mma_h(sacc[2 * ntp], aL, kH);
                mma_h(sacc[2 * ntp + 1], aH, kH + 2);
                mma_h(sacc[2 * ntp + 1], aH, kL + 2);
                mma_h(sacc[2 * ntp + 1], aL, kH + 2);
            }
        }

        // ---- softmax + dropout (mask precomputed), intra-warp ----
        float mx0 = sacc[0][0], mx1 = sacc[0][2];
#pragma unroll
        for (int nt = 0; nt < 8; nt++) {
            mx0 = fmaxf(mx0, fmaxf(sacc[nt][0], sacc[nt][1]));
            mx1 = fmaxf(mx1, fmaxf(sacc[nt][2], sacc[nt][3]));
        }
        mx0 = fmaxf(mx0, __shfl_xor_sync(0xffffffffu, mx0, 1));
        mx0 = fmaxf(mx0, __shfl_xor_sync(0xffffffffu, mx0, 2));
        mx1 = fmaxf(mx1, __shfl_xor_sync(0xffffffffu, mx1, 1));
        mx1 = fmaxf(mx1, __shfl_xor_sync(0xffffffffu, mx1, 2));
        float mn0 = fmaxf(mr0, mx0), mn1 = fmaxf(mr1, mx1);
        float al0 = exp2f((mr0 - mn0) * LOG2E_F);
        float al1 = exp2f((mr1 - mn1) * LOG2E_F);

        uint32_t pHa[8], pHb[8];
        float ls0 = 0.0f, ls1 = 0.0f;
#pragma unroll
        for (int nt = 0; nt < 8; nt++) {
            float p0 = exp2f((sacc[nt][0] - mn0) * LOG2E_F);
            float p1 = exp2f((sacc[nt][1] - mn0) * LOG2E_F);
            float p2 = exp2f((sacc[nt][2] - mn1) * LOG2E_F);
            float p3 = exp2f((sacc[nt][3] - mn1) * LOG2E_F);
            ls0 += p0 + p1; ls1 += p2 + p3;
            uint32_t mb = kmask >> (4 * nt);
            float d0 = (mb & 1u) ? p0 * INV_KEEP : 0.0f;
            float d1 = (mb & 2u) ? p1 * INV_KEEP : 0.0f;
            float d2 = (mb & 4u) ? p2 * INV_KEEP : 0.0f;
            float d3 = (mb & 8u) ? p3 * INV_KEEP : 0.0f;
            pHa[nt] = packh2(d0, d1);
            pHb[nt] = packh2(d2, d3);
        }
        ls0 += __shfl_xor_sync(0xffffffffu, ls0, 1);
        ls0 += __shfl_xor_sync(0xffffffffu, ls0, 2);
        ls1 += __shfl_xor_sync(0xffffffffu, ls1, 1);
        ls1 += __shfl_xor_sync(0xffffffffu, ls1, 2);
        lr0 = lr0 * al0 + ls0;
        lr1 = lr1 * al1 + ls1;
        mr0 = mn0; mr1 = mn1;

#pragma unroll
        for (int nt = 0; nt < 16; nt++) {
            O[nt][0] *= al0; O[nt][1] *= al0;
            O[nt][2] *= al1; O[nt][3] *= al1;
        }

        // ---- PV: O += P * V (vH only; V via ldmatrix.trans) ----
#pragma unroll
        for (int kkp = 0; kkp < 4; kkp++) {
            uint32_t aH[4] = { pHa[2 * kkp], pHb[2 * kkp], pHa[2 * kkp + 1], pHb[2 * kkp + 1] };
#pragma unroll
            for (int ntp = 0; ntp < 8; ntp++) {
                const uint32_t vAddr = vBase + (uint32_t)(kkp * 16 * ROWB + ntp * 32);
                uint32_t vH[4];
                ldsm4t(vH, vAddr);
                mma_h(O[2 * ntp], aH, vH);
                mma_h(O[2 * ntp + 1], aH, vH + 2);
            }
        }
    }

    // ---- final: O / l -> gmem ----
    {
        float inv0 = 1.0f / lr0, inv1 = 1.0f / lr1;
        long row0 = (long)(b * SQ_ + q0 + m0 + g);
        float* o0 = out + row0 * D_ + 2 * tig;
        float* o1 = out + (row0 + 8) * D_ + 2 * tig;
#pragma unroll
        for (int nt = 0; nt < 16; nt++) {
            *(float2*)(o0 + 8 * nt) = make_float2(O[nt][0] * inv0, O[nt][1] * inv0);
            *(float2*)(o1 + 8 * nt) = make_float2(O[nt][2] * inv1, O[nt][3] * inv1);
        }
    }
}

// ---------------------------------------------------------------------------
extern "C" void kernel_launch(void* const* d_in, const int* in_sizes, int n_in,
                              void* d_out, int out_size) {
    const float* q  = (const float*)d_in[0];
    const float* k  = (const float*)d_in[1];
    const float* v  = (const float*)d_in[2];
    const float* sf = (const float*)d_in[3];
    float* out = (float*)d_out;

    prep_kernel<<<3 * NQ4 / 256, 256>>>(q, k, v, sf);

    cudaFuncSetAttribute(attn_fa6_kernel,
                         cudaFuncAttributeMaxDynamicSharedMemorySize, SMEM_TOTAL);
    dim3 grid(SQ_ / MT, B_);
    attn_fa6_kernel<<<grid, NTHREADS, SMEM_TOTAL>>>(out);
}

// round 15
// speedup vs baseline: 1.7724x; 1.1349x over previous
#include <cuda_runtime.h>
#include <cuda_fp16.h>
#include <cstdint>

#define B_    32
#define SQ_   2048
#define SKV_  2048
#define D_    128
#define MT    128
#define NT    64
#define NTILES_H 16        // kv tiles per half (split-KV 2-way)
#define NTHREADS 256
#define NROWS (B_*SQ_)     // 65536

#define INV_KEEP  (1.0f/0.7f)
#define LOG2E_F   1.4426950408889634f
// keep <=> tf_bits < KEEP_THRESH (exact integer form of u < 0.7f, validated R9)
#define KEEP_THRESH 0xB3333400u

#define ROWB 272          // row stride bytes (136 fp16) -> LDSM conflict-free

enum {
  OFF_QH = 0, OFF_QL = 34816,                    // Q planes: 128*272
  OFF_BUF0 = 69632, OFF_BUF1 = 121856,           // K/V double buffer (3 planes each)
  BUF_KH = 0, BUF_KL = 17408, BUF_VH = 34816,
  SMEM_TOTAL = 174080
};

// global scratch: fp16 split planes + split-KV partials
#define NV4 1048576
__device__ uint4 g_QH[NV4], g_QL[NV4];
__device__ uint4 g_KH[NV4], g_KL[NV4];
__device__ uint4 g_VH[NV4];
__device__ float4 g_OP[2 * NROWS * 32];   // unnormalized O partials, 67 MB
__device__ float2 g_ML[2 * NROWS];        // (m, l) per row per half

// ---------------------------------------------------------------------------
// JAX threefry2x32, key=(0,42); bits = x0 ^ x1 (validated R2)
// Round adds routed to IMAD (fma pipe) via opaque multiplier `one`.
// ---------------------------------------------------------------------------
__device__ __forceinline__ uint32_t rotl32(uint32_t x, int d) { return __funnelshift_l(x, x, d); }
__device__ __forceinline__ uint32_t addm(uint32_t a, uint32_t one, uint32_t b) {
    uint32_t r;
    asm("mad.lo.u32 %0, %1, %2, %3;" : "=r"(r) : "r"(a), "r"(one), "r"(b));
    return r;
}
__device__ __forceinline__ void tf_round(uint32_t& x0, uint32_t& x1, int r, uint32_t one) {
    x0 = addm(x0, one, x1);
    x1 = rotl32(x1, r) ^ x0;
}
__device__ __forceinline__ uint32_t tf_bits(uint32_t idx, uint32_t one) {
    const uint32_t ks0 = 0u, ks1 = 42u, ks2 = 0x1BD11BDAu ^ 42u;
    uint32_t x0 = 0u, x1 = idx;
    x0 += ks0; x1 += ks1;
    tf_round(x0, x1, 13, one); tf_round(x0, x1, 15, one); tf_round(x0, x1, 26, one); tf_round(x0, x1, 6, one);
    x0 += ks1; x1 += ks2 + 1u;
    tf_round(x0, x1, 17, one); tf_round(x0, x1, 29, one); tf_round(x0, x1, 16, one); tf_round(x0, x1, 24, one);
    x0 += ks2; x1 += ks0 + 2u;
    tf_round(x0, x1, 13, one); tf_round(x0, x1, 15, one); tf_round(x0, x1, 26, one); tf_round(x0, x1, 6, one);
    x0 += ks0; x1 += ks1 + 3u;
    tf_round(x0, x1, 17, one); tf_round(x0, x1, 29, one); tf_round(x0, x1, 16, one); tf_round(x0, x1, 24, one);
    x0 += ks1; x1 += ks2 + 4u;
    tf_round(x0, x1, 13, one); tf_round(x0, x1, 15, one); tf_round(x0, x1, 26, one); tf_round(x0, x1, 6, one);
    x0 += ks2; x1 += ks0 + 5u;
    return x0 ^ x1;
}

__device__ __forceinline__ uint32_t pack2h(__half a, __half b) {
    return (uint32_t)__half_as_ushort(a) | ((uint32_t)__half_as_ushort(b) << 16);
}
__device__ __forceinline__ uint32_t packh2(float lo, float hi) {
    uint32_t d;
    asm("cvt.rn.f16x2.f32 %0, %1, %2;" : "=r"(d) : "f"(hi), "f"(lo));
    return d;
}
__device__ __forceinline__ void split2h(float x, __half& h, __half& l) {
    h = __float2half_rn(x);
    l = __float2half_rn(x - __half2float(h));
}
__device__ __forceinline__ uint32_t smem_u32(const void* p) {
    uint32_t a;
    asm("{ .reg .u64 t; cvta.to.shared.u64 t, %1; cvt.u32.u64 %0, t; }" : "=r"(a) : "l"(p));
    return a;
}
__device__ __forceinline__ void mma_h(float c[4], const uint32_t a[4], const uint32_t b[2]) {
    asm volatile("mma.sync.aligned.m16n8k16.row.col.f32.f16.f16.f32 "
        "{%0,%1,%2,%3}, {%4,%5,%6,%7}, {%8,%9}, {%0,%1,%2,%3};"
        : "+f"(c[0]), "+f"(c[1]), "+f"(c[2]), "+f"(c[3])
        : "r"(a[0]), "r"(a[1]), "r"(a[2]), "r"(a[3]), "r"(b[0]), "r"(b[1]));
}
__device__ __forceinline__ void ldsm4(uint32_t r[4], uint32_t addr) {
    asm volatile("ldmatrix.sync.aligned.m8n8.x4.shared.b16 {%0,%1,%2,%3}, [%4];"
        : "=r"(r[0]), "=r"(r[1]), "=r"(r[2]), "=r"(r[3]) : "r"(addr));
}
__device__ __forceinline__ void ldsm4t(uint32_t r[4], uint32_t addr) {
    asm volatile("ldmatrix.sync.aligned.m8n8.x4.trans.shared.b16 {%0,%1,%2,%3}, [%4];"
        : "=r"(r[0]), "=r"(r[1]), "=r"(r[2]), "=r"(r[3]) : "r"(addr));
}
__device__ __forceinline__ void cpasync16(uint32_t dst, const void* src) {
    asm volatile("cp.async.cg.shared.global [%0], [%1], 16;" :: "r"(dst), "l"(src));
}
#define CP_COMMIT() asm volatile("cp.async.commit_group;" ::: "memory")
#define CP_WAIT1()  asm volatile("cp.async.wait_group 1;" ::: "memory")
#define CP_WAIT0()  asm volatile("cp.async.wait_group 0;" ::: "memory")

// ---------------------------------------------------------------------------
// Prep: fp16 2-way split of Q (scale folded), K; fp16 high plane of V
// ---------------------------------------------------------------------------
#define NQ4 2097152
__global__ void __launch_bounds__(256) prep_kernel(const float* __restrict__ q,
                                                   const float* __restrict__ k,
                                                   const float* __restrict__ v,
                                                   const float* __restrict__ sf) {
    int i = blockIdx.x * 256 + threadIdx.x;
    if (i < NQ4) {
        float4 x = ((const float4*)q)[i];
        float s = sf[i >> 16];
        x.x *= s; x.y *= s; x.z *= s; x.w *= s;
        __half h[4], l[4];
        split2h(x.x, h[0], l[0]); split2h(x.y, h[1], l[1]);
        split2h(x.z, h[2], l[2]); split2h(x.w, h[3], l[3]);
        ((uint2*)g_QH)[i] = make_uint2(pack2h(h[0], h[1]), pack2h(h[2], h[3]));
        ((uint2*)g_QL)[i] = make_uint2(pack2h(l[0], l[1]), pack2h(l[2], l[3]));
    } else if (i < 2 * NQ4) {
        int j = i - NQ4;
        float4 x = ((const float4*)k)[j];
        __half h[4], l[4];
        split2h(x.x, h[0], l[0]); split2h(x.y, h[1], l[1]);
        split2h(x.z, h[2], l[2]); split2h(x.w, h[3], l[3]);
        ((uint2*)g_KH)[j] = make_uint2(pack2h(h[0], h[1]), pack2h(h[2], h[3]));
        ((uint2*)g_KL)[j] = make_uint2(pack2h(l[0], l[1]), pack2h(l[2], l[3]));
    } else {
        int j = i - 2 * NQ4;
        float4 x = ((const float4*)v)[j];
        ((uint2*)g_VH)[j] = make_uint2(packh2(x.x, x.y), packh2(x.z, x.w));
    }
}

// ---------------------------------------------------------------------------
// Main attention kernel: one (q-tile, batch, kv-half) job -> partial (m,l,O)
// ---------------------------------------------------------------------------
__global__ void __launch_bounds__(NTHREADS, 1)
attn_fa7_kernel(uint32_t one) {
    extern __shared__ char smem[];
    const uint32_t sb = smem_u32(smem);

    const int b    = blockIdx.y;
    const int q0   = blockIdx.x * MT;
    const int half = blockIdx.z;
    const int tid  = threadIdx.x;
    const int lane = tid & 31;
    const int w    = tid >> 5;
    const int g    = lane >> 2;
    const int tig  = lane & 3;
    const int m0   = w * 16;
    const int l7   = lane & 7;
    const int b3   = (lane >> 3) & 1;
    const int b4   = lane >> 4;

    const uint32_t aBase   = sb + OFF_QH + (uint32_t)((m0 + l7 + 8 * b3) * ROWB + 16 * b4);
    const uint32_t kLaneOf = (uint32_t)((l7 + 8 * b4) * ROWB + 16 * b3);
    const uint32_t vLaneOf = (uint32_t)((l7 + 8 * b3) * ROWB + 16 * b4);

    // ---- stage Q planes (pure LDG.128 -> STS.128) ----
    {
        const int qrow0 = (b * SQ_ + q0) * 16;
#pragma unroll
        for (int c = 0; c < 8; c++) {
            int f = tid + 256 * c;
            int rr = f >> 4, c4 = f & 15;
            *(uint4*)(smem + OFF_QH + rr * ROWB + c4 * 16) = g_QH[qrow0 + rr * 16 + c4];
            *(uint4*)(smem + OFF_QL + rr * ROWB + c4 * 16) = g_QL[qrow0 + rr * 16 + c4];
        }
    }

    float O[16][4];
#pragma unroll
    for (int nt = 0; nt < 16; nt++) { O[nt][0] = O[nt][1] = O[nt][2] = O[nt][3] = 0.0f; }
    float mr0 = -3.402823466e38f, mr1 = -3.402823466e38f, lr0 = 0.0f, lr1 = 0.0f;

    const uint32_t rowbase = (uint32_t)(b * SQ_ + q0 + m0);
    const int bkb = b * SKV_ + half * (NTILES_H * NT);   // this half's kv row base

    // prologue: stage tile 0 of this half into buf0
    {
        const uint4* gp[3] = {g_KH, g_KL, g_VH};
#pragma unroll
        for (int s = 0; s < 3; s++)
#pragma unroll
            for (int c = 0; c < 4; c++) {
                int f = tid + 256 * c;
                int rr = f >> 4, c4 = f & 15;
                cpasync16(sb + OFF_BUF0 + (uint32_t)(s * 17408 + rr * ROWB + c4 * 16),
                          &gp[s][(bkb + rr) * 16 + c4]);
            }
        CP_COMMIT();
    }

    for (int t = 0; t < NTILES_H; t++) {
        const int kv0 = half * (NTILES_H * NT) + t * NT;
        __syncthreads();

        if (t + 1 < NTILES_H) {
            const uint32_t nbuf = sb + (((t + 1) & 1) ? OFF_BUF1 : OFF_BUF0);
            const int bk = bkb + (t + 1) * NT;
            const uint4* gp[3] = {g_KH, g_KL, g_VH};
#pragma unroll
            for (int s = 0; s < 3; s++)
#pragma unroll
                for (int c = 0; c < 4; c++) {
                    int f = tid + 256 * c;
                    int rr = f >> 4, c4 = f & 15;
                    cpasync16(nbuf + (uint32_t)(s * 17408 + rr * ROWB + c4 * 16),
                              &gp[s][(bk + rr) * 16 + c4]);
                }
            CP_COMMIT();
            CP_WAIT1();
        } else {
            CP_WAIT0();
        }
        __syncthreads();

        const uint32_t bufb  = sb + ((t & 1) ? OFF_BUF1 : OFF_BUF0);
        const uint32_t kBase = bufb + BUF_KH + kLaneOf;
        const uint32_t vBase = bufb + BUF_VH + vLaneOf;

        // ---- QK MMAs (3 fp16 passes: HH, HL, LH) + threefry interleaved ----
        float sacc[8][4];
#pragma unroll
        for (int nt = 0; nt < 8; nt++) { sacc[nt][0] = sacc[nt][1] = sacc[nt][2] = sacc[nt][3] = 0.0f; }

        uint32_t kmask = 0;
        const uint32_t idx00 = (rowbase + (uint32_t)g) * (uint32_t)SKV_
                             + (uint32_t)(kv0 + 2 * tig);

#pragma unroll
        for (int k8 = 0; k8 < 8; k8++) {
            {   // dropout mask for n-tile k8 (overlaps HMMA) — R11 shape
                uint32_t ia = idx00 + (uint32_t)(8 * k8);
                uint32_t ib = ia + 8u * (uint32_t)SKV_;
                uint32_t q0b = (tf_bits(ia, one)      < KEEP_THRESH) ? 1u : 0u;
                uint32_t q1b = (tf_bits(ia + 1u, one) < KEEP_THRESH) ? 2u : 0u;
                uint32_t q2b = (tf_bits(ib, one)      < KEEP_THRESH) ? 4u : 0u;
                uint32_t q3b = (tf_bits(ib + 1u, one) < KEEP_THRESH) ? 8u : 0u;
                kmask |= (q0b | q1b | q2b | q3b) << (4 * k8);
            }
            uint32_t aH[4], aL[4];
            const uint32_t aAddr = aBase + (uint32_t)(k8 * 32);
            ldsm4(aH, aAddr);
            ldsm4(aL, aAddr + 34816u);
#pragma unroll
            for (int ntp = 0; ntp < 4; ntp++) {
                const uint32_t kAddr = kBase + (uint32_t)(ntp * 16 * ROWB + k8 * 32);
                uint32_t kH[4], kL[4];
                ldsm4(kH, kAddr);
                ldsm4(kL, kAddr + 17408u);
                mma_h(sacc[2 * ntp], aH, kH);
                mma_h(sacc[2 * ntp], aH, kL);
                mma_h(sacc[2 * ntp], aL, kH);
                mma_h(sacc[2 * ntp + 1], aH, kH + 2);
                mma_h(sacc[2 * ntp + 1], aH, kL + 2);
                mma_h(sacc[2 * ntp + 1], aL, kH + 2);
            }
        }

        // ---- softmax + dropout (mask precomputed), intra-warp ----
        float mx0 = sacc[0][0], mx1 = sacc[0][2];
#pragma unroll
        for (int nt = 0; nt < 8; nt++) {
            mx0 = fmaxf(mx0, fmaxf(sacc[nt][0], sacc[nt][1]));
            mx1 = fmaxf(mx1, fmaxf(sacc[nt][2], sacc[nt][3]));
        }
        mx0 = fmaxf(mx0, __shfl_xor_sync(0xffffffffu, mx0, 1));
        mx0 = fmaxf(mx0, __shfl_xor_sync(0xffffffffu, mx0, 2));
        mx1 = fmaxf(mx1, __shfl_xor_sync(0xffffffffu, mx1, 1));
        mx1 = fmaxf(mx1, __shfl_xor_sync(0xffffffffu, mx1, 2));
        float mn0 = fmaxf(mr0, mx0), mn1 = fmaxf(mr1, mx1);
        float al0 = exp2f((mr0 - mn0) * LOG2E_F);
        float al1 = exp2f((mr1 - mn1) * LOG2E_F);

        uint32_t pHa[8], pHb[8];
        float ls0 = 0.0f, ls1 = 0.0f;
#pragma unroll
        for (int nt = 0; nt < 8; nt++) {
            float p0 = exp2f((sacc[nt][0] - mn0) * LOG2E_F);
            float p1 = exp2f((sacc[nt][1] - mn0) * LOG2E_F);
            float p2 = exp2f((sacc[nt][2] - mn1) * LOG2E_F);
            float p3 = exp2f((sacc[nt][3] - mn1) * LOG2E_F);
            ls0 += p0 + p1; ls1 += p2 + p3;
            uint32_t mb = kmask >> (4 * nt);
            float d0 = (mb & 1u) ? p0 * INV_KEEP : 0.0f;
            float d1 = (mb & 2u) ? p1 * INV_KEEP : 0.0f;
            float d2 = (mb & 4u) ? p2 * INV_KEEP : 0.0f;
            float d3 = (mb & 8u) ? p3 * INV_KEEP : 0.0f;
            pHa[nt] = packh2(d0, d1);
            pHb[nt] = packh2(d2, d3);
        }
        ls0 += __shfl_xor_sync(0xffffffffu, ls0, 1);
        ls0 += __shfl_xor_sync(0xffffffffu, ls0, 2);
        ls1 += __shfl_xor_sync(0xffffffffu, ls1, 1);
        ls1 += __shfl_xor_sync(0xffffffffu, ls1, 2);
        lr0 = lr0 * al0 + ls0;
        lr1 = lr1 * al1 + ls1;
        mr0 = mn0; mr1 = mn1;

#pragma unroll
        for (int nt = 0; nt < 16; nt++) {
            O[nt][0] *= al0; O[nt][1] *= al0;
            O[nt][2] *= al1; O[nt][3] *= al1;
        }

        // ---- PV: O += P * V (vH only; V via ldmatrix.trans) ----
#pragma unroll
        for (int kkp = 0; kkp < 4; kkp++) {
            uint32_t aH[4] = { pHa[2 * kkp], pHb[2 * kkp], pHa[2 * kkp + 1], pHb[2 * kkp + 1] };
#pragma unroll
            for (int ntp = 0; ntp < 8; ntp++) {
                const uint32_t vAddr = vBase + (uint32_t)(kkp * 16 * ROWB + ntp * 32);
                uint32_t vH[4];
                ldsm4t(vH, vAddr);
                mma_h(O[2 * ntp], aH, vH);
                mma_h(O[2 * ntp + 1], aH, vH + 2);
            }
        }
    }

    // ---- write partials (unnormalized O, plus (m, l) per row) ----
    {
        int row0 = b * SQ_ + q0 + m0 + g;
        float* o0 = (float*)(g_OP + (half * NROWS + row0) * 32) + 2 * tig;
        float* o1 = (float*)(g_OP + (half * NROWS + row0 + 8) * 32) + 2 * tig;
#pragma unroll
        for (int nt = 0; nt < 16; nt++) {
            *(float2*)(o0 + 8 * nt) = make_float2(O[nt][0], O[nt][1]);
            *(float2*)(o1 + 8 * nt) = make_float2(O[nt][2], O[nt][3]);
        }
        if (tig == 0) {
            g_ML[half * NROWS + row0]     = make_float2(mr0, lr0);
            g_ML[half * NROWS + row0 + 8] = make_float2(mr1, lr1);
        }
    }
}

// ---------------------------------------------------------------------------
// Merge kernel: combine the two kv-half partials, normalize, write out
// ---------------------------------------------------------------------------
__global__ void __launch_bounds__(256) merge_kernel(float* __restrict__ out) {
    int gid = blockIdx.x * 256 + threadIdx.x;   // NROWS*32 float4 chunks
    int row = gid >> 5;
    float2 ml0 = g_ML[row], ml1 = g_ML[NROWS + row];
    float m  = fmaxf(ml0.x, ml1.x);
    float w0 = exp2f((ml0.x - m) * LOG2E_F);
    float w1 = exp2f((ml1.x - m) * LOG2E_F);
    float inv = 1.0f / (ml0.y * w0 + ml1.y * w1);
    float a = w0 * inv, c = w1 * inv;
    float4 o0 = g_OP[gid], o1 = g_OP[NROWS * 32 + gid];
    float4 r;
    r.x = o0.x * a + o1.x * c;
    r.y = o0.y * a + o1.y * c;
    r.z = o0.z * a + o1.z * c;
    r.w = o0.w * a + o1.w * c;
    ((float4*)out)[gid] = r;
}

// ---------------------------------------------------------------------------
extern "C" void kernel_launch(void* const* d_in, const int* in_sizes, int n_in,
                              void* d_out, int out_size) {
    const float* q  = (const float*)d_in[0];
    const float* k  = (const float*)d_in[1];
    const float* v  = (const float*)d_in[2];
    const float* sf = (const float*)d_in[3];
    float* out = (float*)d_out;

    prep_kernel<<<3 * NQ4 / 256, 256>>>(q, k, v, sf);

    cudaFuncSetAttribute(attn_fa7_kernel,
                         cudaFuncAttributeMaxDynamicSharedMemorySize, SMEM_TOTAL);
    dim3 grid(SQ_ / MT, B_, 2);
    attn_fa7_kernel<<<grid, NTHREADS, SMEM_TOTAL>>>(1u);

    merge_kernel<<<NROWS * 32 / 256, 256>>>(out);
}